// round 9
// baseline (speedup 1.0000x reference)
#include <cuda_runtime.h>
#include <cuda_fp16.h>
#include <cstdint>
#include <math.h>

#define NOUT 255
#define NCHUNK 9

// ------------- prepped weights (device globals) -------------
// Per chunk c: B tile 64(k) x 256(n) fp16, pre-swizzled:
//   byte(k,n) = k*512 + (((n>>3) ^ (k&7))<<4) + ((n*2)&15)
__device__ __half g_B[NCHUNK * 64 * 256];
__device__ float g_wt[256];

__global__ void prep_W(const float* __restrict__ W) {
    int c = blockIdx.x;   // chunk/tap
    int k = blockIdx.y;   // 0..63
    int n = threadIdx.x;  // 0..255
    float v = 0.0f;
    if (n < NOUT) v = W[n * 577 + 1 + c * 64 + k];
    uint32_t byte = (uint32_t)k * 512 + ((((uint32_t)n >> 3) ^ (k & 7)) << 4) + ((n * 2) & 15);
    g_B[(size_t)c * 16384 + byte / 2] = __float2half(v);
    if (c == 0 && k == 0) g_wt[n] = (n < NOUT) ? W[n * 577] : 0.0f;
}

// ------------- smem layout -------------
// stage: A 8KB + B 32KB = 40KB, double buffered = 80KB
#define STAGE_SZ 40960
#define OFF_A 0
#define OFF_B 8192
#define OFF_STC  81920
#define OFF_WT   82176
#define OFF_BIAS 83200
#define OFF_SSP  84224
#define SMEM_BYTES 85248

// ------------- PTX helpers -------------
__device__ __forceinline__ uint32_t smem_u32(const void* p) {
    uint32_t a;
    asm("{ .reg .u64 t; cvta.to.shared.u64 t, %1; cvt.u32.u64 %0, t; }" : "=r"(a) : "l"(p));
    return a;
}
__device__ __forceinline__ void cp16(uint32_t dst, const void* src) {
    asm volatile("cp.async.cg.shared.global [%0], [%1], 16;" :: "r"(dst), "l"(src));
}
__device__ __forceinline__ void cp_commit() { asm volatile("cp.async.commit_group;"); }
__device__ __forceinline__ void cp_wait_all() { asm volatile("cp.async.wait_group 0;"); }

__device__ __forceinline__ void ldsm4(uint32_t* r, uint32_t a) {
    asm volatile("ldmatrix.sync.aligned.m8n8.x4.shared.b16 {%0,%1,%2,%3}, [%4];"
                 : "=r"(r[0]), "=r"(r[1]), "=r"(r[2]), "=r"(r[3]) : "r"(a));
}
__device__ __forceinline__ void ldsm4t(uint32_t* r, uint32_t a) {
    asm volatile("ldmatrix.sync.aligned.m8n8.x4.trans.shared.b16 {%0,%1,%2,%3}, [%4];"
                 : "=r"(r[0]), "=r"(r[1]), "=r"(r[2]), "=r"(r[3]) : "r"(a));
}
__device__ __forceinline__ void mma16816(float* d, const uint32_t* a, const uint32_t* b) {
    asm volatile(
        "mma.sync.aligned.m16n8k16.row.col.f32.f16.f16.f32 "
        "{%0,%1,%2,%3}, {%4,%5,%6,%7}, {%8,%9}, {%0,%1,%2,%3};"
        : "+f"(d[0]), "+f"(d[1]), "+f"(d[2]), "+f"(d[3])
        : "r"(a[0]), "r"(a[1]), "r"(a[2]), "r"(a[3]), "r"(b[0]), "r"(b[1]));
}

__device__ __forceinline__ int clamp64(int v) { return v < 0 ? 0 : (v > 63 ? 63 : v); }

// ------------- main kernel: 1 image row (64 pixels) x 256 outputs per CTA -------------
__global__ void __launch_bounds__(256, 2)
hyp_hmma(const float* __restrict__ x,
         const float* __restrict__ bias,
         float* __restrict__ out) {
    extern __shared__ char smem[];
    const uint32_t sb = smem_u32(smem);
    float* stc   = (float*)(smem + OFF_STC);
    float* swt   = (float*)(smem + OFF_WT);
    float* sbias = (float*)(smem + OFF_BIAS);
    float* ssp   = (float*)(smem + OFF_SSP);

    const int tid  = threadIdx.x;
    const int lane = tid & 31;
    const int warp = tid >> 5;
    const int wm = warp >> 2;          // 0..1 -> m offset 32*wm
    const int wn = warp & 3;           // 0..3 -> n offset 64*wn

    const int blk  = blockIdx.x;       // 2048 = 32 batches * 64 rows
    const int bimg = blk >> 6;
    const int y0   = blk & 63;         // single image row
    const float* ximg = x + (size_t)bimg * 64 * 64 * 65;

    // aux: time weights, bias, t_cat
    swt[tid]   = g_wt[tid];
    sbias[tid] = (tid < NOUT) ? bias[tid] : 0.0f;
    if (tid < 64) {
        float s = 0.0f;
#pragma unroll
        for (int dy = -1; dy <= 1; dy++)
#pragma unroll
            for (int dx = -1; dx <= 1; dx++) {
                int yy = clamp64(y0 + dy);
                int xx = clamp64(tid + dx);
                float t = __ldg(ximg + ((size_t)yy * 64 + xx) * 65);
                s = fmaf(t, t, s);
            }
        stc[tid] = sqrtf(s - 8.0f);
    }

    // ---- A conversion (fp16) into stage s for tap c: 64 px x 64 ch ----
    auto convertA = [&](int c, int s) {
        const int dy = c / 3 - 1, dx = c % 3 - 1;
        const int pl = tid >> 2;            // pixel 0..63
        const int c0 = (tid & 3) * 16;      // 16 channels per thread
        const int yy = clamp64(y0 + dy);
        const int xx = clamp64(pl + dx);
        const float* src = ximg + ((size_t)yy * 64 + xx) * 65 + 1 + c0;
        char* aP = smem + s * STAGE_SZ + OFF_A;
        uint32_t w[8];
#pragma unroll
        for (int u = 0; u < 8; u++) {
            float v0 = __ldg(src + 2 * u);
            float v1 = __ldg(src + 2 * u + 1);
            __half2 hv = __floats2half2_rn(v0, v1);
            w[u] = *(uint32_t*)&hv;
        }
        const int k4 = (tid & 3) * 2;
        uint32_t b0 = (uint32_t)pl * 128 + ((((uint32_t)(k4 + 0)) ^ (pl & 7)) << 4);
        uint32_t b1 = (uint32_t)pl * 128 + ((((uint32_t)(k4 + 1)) ^ (pl & 7)) << 4);
        *(uint4*)(aP + b0) = make_uint4(w[0], w[1], w[2], w[3]);
        *(uint4*)(aP + b1) = make_uint4(w[4], w[5], w[6], w[7]);
    };

    // ---- B cp.async into stage s for tap c (32KB, 128B/thread) ----
    auto loadB = [&](int c, int s) {
        const char* srcB = (const char*)g_B + (size_t)c * 32768;
        uint32_t dstB = sb + s * STAGE_SZ + OFF_B;
#pragma unroll
        for (int r = 0; r < 8; r++) {
            int u = tid + r * 256;
            cp16(dstB + u * 16, srcB + u * 16);
        }
    };

    float acc[2][8][4];
#pragma unroll
    for (int i = 0; i < 2; i++)
#pragma unroll
        for (int j = 0; j < 8; j++)
#pragma unroll
            for (int r = 0; r < 4; r++) acc[i][j][r] = 0.0f;

    // prologue: stage 0
    loadB(0, 0);
    cp_commit();
    convertA(0, 0);

    for (int c = 0; c < NCHUNK; c++) {
        cp_wait_all();
        __syncthreads();
        int s = c & 1;
        if (c + 1 < NCHUNK) {
            loadB(c + 1, s ^ 1);
            cp_commit();
            convertA(c + 1, s ^ 1);
        }

        const uint32_t baseA = sb + s * STAGE_SZ;
        const int selm = (lane >> 3) & 1;
        const int selk = lane >> 4;
        const int lr   = lane & 7;

#pragma unroll
        for (int ks = 0; ks < 4; ks++) {
            const int k0 = ks * 16;
            uint32_t ah[2][4];
#pragma unroll
            for (int i = 0; i < 2; i++) {
                int m  = wm * 32 + i * 16 + selm * 8 + lr;
                int kk = k0 + selk * 8;
                uint32_t byte = (uint32_t)m * 128 + ((((uint32_t)(kk >> 3)) ^ (m & 7)) << 4);
                ldsm4(ah[i], baseA + OFF_A + byte);
            }
#pragma unroll
            for (int h = 0; h < 2; h++) {
                uint32_t bh[4][2];
#pragma unroll
                for (int pr = 0; pr < 2; pr++) {
                    int n0 = wn * 64 + h * 32 + pr * 16;
                    int kb = k0 + selm * 8 + lr;
                    int nn = n0 + selk * 8;
                    uint32_t byte = (uint32_t)kb * 512 + ((((uint32_t)(nn >> 3)) ^ (kb & 7)) << 4);
                    uint32_t r4[4];
                    ldsm4t(r4, baseA + OFF_B + byte);
                    bh[pr * 2][0] = r4[0]; bh[pr * 2][1] = r4[1];
                    bh[pr * 2 + 1][0] = r4[2]; bh[pr * 2 + 1][1] = r4[3];
                }
#pragma unroll
                for (int i = 0; i < 2; i++)
#pragma unroll
                    for (int j = 0; j < 4; j++)
                        mma16816(acc[i][h * 4 + j], ah[i], bh[j]);
            }
        }
    }

    // ---------------- epilogue: direct stores, no smem staging ----------------
    const int q  = lane >> 2;
    const int c2 = (lane & 3) * 2;
    const size_t gbase = (size_t)blk * 64 * 256;

#pragma unroll
    for (int i = 0; i < 2; i++) {
#pragma unroll
        for (int rr = 0; rr < 2; rr++) {
            int p = wm * 32 + i * 16 + rr * 8 + q;    // 0..63
            float tc = stc[p];
            float ssq = 0.0f;
            float* zrow = out + gbase + (size_t)p * 256 + 1;
#pragma unroll
            for (int j = 0; j < 8; j++) {
                int o0 = wn * 64 + j * 8 + c2;
                float z0 = acc[i][j][rr * 2 + 0] + tc * swt[o0] + sbias[o0];
                float z1 = acc[i][j][rr * 2 + 1] + tc * swt[o0 + 1] + sbias[o0 + 1];
                ssq = fmaf(z0, z0, fmaf(z1, z1, ssq));
                zrow[o0] = z0;
                if (o0 + 1 < NOUT) zrow[o0 + 1] = z1;
            }
            ssq += __shfl_xor_sync(0xffffffffu, ssq, 1);
            ssq += __shfl_xor_sync(0xffffffffu, ssq, 2);
            if ((lane & 3) == 0) ssp[p * 4 + wn] = ssq;
        }
    }
    __syncthreads();
    if (tid < 64) {
        float ssum = ssp[tid * 4] + ssp[tid * 4 + 1] + ssp[tid * 4 + 2] + ssp[tid * 4 + 3];
        out[gbase + (size_t)tid * 256] = sqrtf(1.0f + ssum);
    }
}

// ------------- launch -------------
extern "C" void kernel_launch(void* const* d_in, const int* in_sizes, int n_in,
                              void* d_out, int out_size) {
    const float* x = (const float*)d_in[0];   // (32,64,64,65)
    const float* W = (const float*)d_in[1];   // (255,577)
    const float* b = (const float*)d_in[2];   // (255)
    float* out = (float*)d_out;               // (32,64,64,256)

    prep_W<<<dim3(NCHUNK, 64), 256>>>(W);

    cudaFuncSetAttribute(hyp_hmma, cudaFuncAttributeMaxDynamicSharedMemorySize, SMEM_BYTES);
    hyp_hmma<<<2048, 256, SMEM_BYTES>>>(x, b, out);
}

// round 10
// speedup vs baseline: 1.0961x; 1.0961x over previous
#include <cuda_runtime.h>
#include <cuda_fp16.h>
#include <cstdint>
#include <math.h>

#define NOUT 255
#define NCHUNK 9

// ------------- prepped weights -------------
// Per chunk c: B tile 64(k) x 256(n) fp16, pre-swizzled:
//   byte(k,n) = k*512 + (((n>>3) ^ (k&7))<<4) + ((n*2)&15)
__device__ __half g_B[NCHUNK * 64 * 256];
__device__ float g_wt[256];

__global__ void prep_W(const float* __restrict__ W) {
    int c = blockIdx.x;
    int k = blockIdx.y;
    int n = threadIdx.x;
    float v = 0.0f;
    if (n < NOUT) v = W[n * 577 + 1 + c * 64 + k];
    uint32_t byte = (uint32_t)k * 512 + ((((uint32_t)n >> 3) ^ (k & 7)) << 4) + ((n * 2) & 15);
    g_B[(size_t)c * 16384 + byte / 2] = __float2half(v);
    if (c == 0 && k == 0) g_wt[n] = (n < NOUT) ? W[n * 577] : 0.0f;
}

// ------------- smem layout -------------
// A buffer: 4 image rows x 66 padded px x 64 ch fp16, m-major 128B rows = 33792 B
// B stages: 2 x 32768
#define OFF_A    0
#define A_BYTES  (4 * 66 * 128)
#define OFF_B    33792
#define B_STAGE  32768
#define OFF_STC  (33792 + 2 * 32768)          // 99328: 128 floats
#define OFF_WT   (OFF_STC + 512)
#define OFF_BIAS (OFF_WT + 1024)
#define OFF_SSP  (OFF_BIAS + 1024)            // 128*4 floats
#define SMEM_BYTES (OFF_SSP + 2048)

// ------------- PTX helpers -------------
__device__ __forceinline__ uint32_t smem_u32(const void* p) {
    uint32_t a;
    asm("{ .reg .u64 t; cvta.to.shared.u64 t, %1; cvt.u32.u64 %0, t; }" : "=r"(a) : "l"(p));
    return a;
}
__device__ __forceinline__ void cp16(uint32_t dst, const void* src) {
    asm volatile("cp.async.cg.shared.global [%0], [%1], 16;" :: "r"(dst), "l"(src));
}
__device__ __forceinline__ void cp_commit() { asm volatile("cp.async.commit_group;"); }
__device__ __forceinline__ void cp_wait_all() { asm volatile("cp.async.wait_group 0;"); }

__device__ __forceinline__ void ldsm4(uint32_t* r, uint32_t a) {
    asm volatile("ldmatrix.sync.aligned.m8n8.x4.shared.b16 {%0,%1,%2,%3}, [%4];"
                 : "=r"(r[0]), "=r"(r[1]), "=r"(r[2]), "=r"(r[3]) : "r"(a));
}
__device__ __forceinline__ void ldsm4t(uint32_t* r, uint32_t a) {
    asm volatile("ldmatrix.sync.aligned.m8n8.x4.trans.shared.b16 {%0,%1,%2,%3}, [%4];"
                 : "=r"(r[0]), "=r"(r[1]), "=r"(r[2]), "=r"(r[3]) : "r"(a));
}
__device__ __forceinline__ void mma16816(float* d, const uint32_t* a, const uint32_t* b) {
    asm volatile(
        "mma.sync.aligned.m16n8k16.row.col.f32.f16.f16.f32 "
        "{%0,%1,%2,%3}, {%4,%5,%6,%7}, {%8,%9}, {%0,%1,%2,%3};"
        : "+f"(d[0]), "+f"(d[1]), "+f"(d[2]), "+f"(d[3])
        : "r"(a[0]), "r"(a[1]), "r"(a[2]), "r"(a[3]), "r"(b[0]), "r"(b[1]));
}

__device__ __forceinline__ int clamp64(int v) { return v < 0 ? 0 : (v > 63 ? 63 : v); }

// ------------- main kernel: 2 image rows (128 px) x 256 outputs per CTA -------------
// 8 warps, warp tile 64x64 (2m x 4n)
__global__ void __launch_bounds__(256, 1)
hyp_hmma(const float* __restrict__ x,
         const float* __restrict__ bias,
         float* __restrict__ out) {
    extern __shared__ char smem[];
    const uint32_t sb = smem_u32(smem);
    float* stc   = (float*)(smem + OFF_STC);
    float* swt   = (float*)(smem + OFF_WT);
    float* sbias = (float*)(smem + OFF_BIAS);
    float* ssp   = (float*)(smem + OFF_SSP);

    const int tid  = threadIdx.x;
    const int lane = tid & 31;
    const int warp = tid >> 5;
    const int wm = warp >> 2;          // 0..1 -> m offset 64*wm (= image row within CTA)
    const int wn = warp & 3;           // 0..3 -> n offset 64*wn

    const int blk  = blockIdx.x;       // 1024 = 32 batches * 32 row-pairs
    const int bimg = blk >> 5;
    const int y0   = (blk & 31) * 2;   // 2 image rows
    const float* ximg = x + (size_t)bimg * 64 * 64 * 65;

    // aux: time weights, bias, t_cat
    swt[tid]   = g_wt[tid];
    sbias[tid] = (tid < NOUT) ? bias[tid] : 0.0f;
    if (tid < 128) {
        int iy = tid >> 6, ix = tid & 63;
        float s = 0.0f;
#pragma unroll
        for (int dy = -1; dy <= 1; dy++)
#pragma unroll
            for (int dx = -1; dx <= 1; dx++) {
                int yy = clamp64(y0 + iy + dy);
                int xx = clamp64(ix + dx);
                float t = __ldg(ximg + ((size_t)yy * 64 + xx) * 65);
                s = fmaf(t, t, s);
            }
        stc[tid] = sqrtf(s - 8.0f);
    }

    // ---- B cp.async into stage s for tap c (32KB, 128B/thread) ----
    auto loadB = [&](int c, int s) {
        const char* srcB = (const char*)g_B + (size_t)c * 32768;
        uint32_t dstB = sb + OFF_B + s * B_STAGE;
#pragma unroll
        for (int r = 0; r < 8; r++) {
            int u = tid + r * 256;
            cp16(dstB + u * 16, srcB + u * 16);
        }
    };

    // prologue: first B stage + one-time A conversion (4 rows x 66 px x 64 ch)
    loadB(0, 0);
    cp_commit();
    {
        char* aP = smem + OFF_A;
        for (int idx = tid; idx < 4 * 66 * 4; idx += 256) {
            int brow = idx >> 2;            // 0..263
            int q    = idx & 3;             // 16-channel quarter
            int r    = brow / 66;
            int col  = brow - r * 66;
            int yy = clamp64(y0 + r - 1);
            int xx = clamp64(col - 1);
            const float* src = ximg + ((size_t)yy * 64 + xx) * 65 + 1 + q * 16;
            uint32_t w[8];
#pragma unroll
            for (int u = 0; u < 8; u++) {
                float v0 = __ldg(src + 2 * u);
                float v1 = __ldg(src + 2 * u + 1);
                __half2 hv = __floats2half2_rn(v0, v1);
                w[u] = *(uint32_t*)&hv;
            }
            int kc = q * 2;
            uint32_t b0 = (uint32_t)brow * 128 + ((((uint32_t)(kc + 0)) ^ (brow & 7)) << 4);
            uint32_t b1 = (uint32_t)brow * 128 + ((((uint32_t)(kc + 1)) ^ (brow & 7)) << 4);
            *(uint4*)(aP + b0) = make_uint4(w[0], w[1], w[2], w[3]);
            *(uint4*)(aP + b1) = make_uint4(w[4], w[5], w[6], w[7]);
        }
    }

    float acc[4][8][4];
#pragma unroll
    for (int i = 0; i < 4; i++)
#pragma unroll
        for (int j = 0; j < 8; j++)
#pragma unroll
            for (int r = 0; r < 4; r++) acc[i][j][r] = 0.0f;

    const int selm = (lane >> 3) & 1;
    const int selk = lane >> 4;
    const int lr   = lane & 7;

    for (int c = 0; c < NCHUNK; c++) {
        cp_wait_all();
        __syncthreads();
        int s = c & 1;
        if (c + 1 < NCHUNK) {
            loadB(c + 1, s ^ 1);
            cp_commit();
        }

        // tap offsets: A-tile row m (in buffer) = (wm + dy + 1)*66 + dx + 1 + inner
        const int dy = c / 3 - 1, dx = c % 3 - 1;
        const int arow0 = (wm + dy + 1) * 66 + dx + 1;
        const uint32_t baseB = sb + OFF_B + s * B_STAGE;

#pragma unroll
        for (int ks = 0; ks < 4; ks++) {
            const int k0 = ks * 16;
            const int kk = k0 + selk * 8;
            uint32_t ah[4][4];
#pragma unroll
            for (int i = 0; i < 4; i++) {
                int row = arow0 + i * 16 + selm * 8 + lr;
                uint32_t byte = (uint32_t)row * 128 + ((((uint32_t)(kk >> 3)) ^ (row & 7)) << 4);
                ldsm4(ah[i], sb + OFF_A + byte);
            }
            const int kb = k0 + selm * 8 + lr;
#pragma unroll
            for (int jn = 0; jn < 4; jn++) {
                int n0 = wn * 64 + jn * 16;
                int nn = n0 + selk * 8;
                uint32_t byte = (uint32_t)kb * 512 + ((((uint32_t)(nn >> 3)) ^ (kb & 7)) << 4);
                uint32_t r4[4];
                ldsm4t(r4, baseB + byte);
                uint32_t bf0[2] = {r4[0], r4[1]};
                uint32_t bf1[2] = {r4[2], r4[3]};
#pragma unroll
                for (int i = 0; i < 4; i++) {
                    mma16816(acc[i][jn * 2 + 0], ah[i], bf0);
                    mma16816(acc[i][jn * 2 + 1], ah[i], bf1);
                }
            }
        }
    }

    // ---------------- epilogue: direct stores ----------------
    const int q  = lane >> 2;
    const int c2 = (lane & 3) * 2;
    const size_t gbase = (size_t)blk * 128 * 256;

#pragma unroll
    for (int i = 0; i < 4; i++) {
#pragma unroll
        for (int rr = 0; rr < 2; rr++) {
            int p = wm * 64 + i * 16 + rr * 8 + q;    // 0..127
            float tc = stc[p];
            float ssq = 0.0f;
            float* zrow = out + gbase + (size_t)p * 256 + 1;
#pragma unroll
            for (int j = 0; j < 8; j++) {
                int o0 = wn * 64 + j * 8 + c2;
                float z0 = acc[i][j][rr * 2 + 0] + tc * swt[o0] + sbias[o0];
                float z1 = acc[i][j][rr * 2 + 1] + tc * swt[o0 + 1] + sbias[o0 + 1];
                ssq = fmaf(z0, z0, fmaf(z1, z1, ssq));
                zrow[o0] = z0;
                if (o0 + 1 < NOUT) zrow[o0 + 1] = z1;
            }
            ssq += __shfl_xor_sync(0xffffffffu, ssq, 1);
            ssq += __shfl_xor_sync(0xffffffffu, ssq, 2);
            if ((lane & 3) == 0) ssp[p * 4 + wn] = ssq;
        }
    }
    __syncthreads();
    if (tid < 128) {
        float ssum = ssp[tid * 4] + ssp[tid * 4 + 1] + ssp[tid * 4 + 2] + ssp[tid * 4 + 3];
        out[gbase + (size_t)tid * 256] = sqrtf(1.0f + ssum);
    }
}

// ------------- launch -------------
extern "C" void kernel_launch(void* const* d_in, const int* in_sizes, int n_in,
                              void* d_out, int out_size) {
    const float* x = (const float*)d_in[0];   // (32,64,64,65)
    const float* W = (const float*)d_in[1];   // (255,577)
    const float* b = (const float*)d_in[2];   // (255)
    float* out = (float*)d_out;               // (32,64,64,256)

    prep_W<<<dim3(NCHUNK, 64), 256>>>(W);

    cudaFuncSetAttribute(hyp_hmma, cudaFuncAttributeMaxDynamicSharedMemorySize, SMEM_BYTES);
    hyp_hmma<<<1024, 256, SMEM_BYTES>>>(x, b, out);
}

// round 11
// speedup vs baseline: 1.1014x; 1.0048x over previous
#include <cuda_runtime.h>
#include <cuda_fp16.h>
#include <cstdint>
#include <math.h>

#define NOUT 255
#define NCHUNK 9

// ------------- prepped weights -------------
// Per chunk c: B tile 64(k) x 256(n) fp16, pre-swizzled:
//   byte(k,n) = k*512 + (((n>>3) ^ (k&7))<<4) + ((n*2)&15)
__device__ __half g_B[NCHUNK * 64 * 256];
__device__ float g_wt[256];

__global__ void prep_W(const float* __restrict__ W) {
    int c = blockIdx.x;
    int k = blockIdx.y;
    int n = threadIdx.x;
    float v = 0.0f;
    if (n < NOUT) v = W[n * 577 + 1 + c * 64 + k];
    uint32_t byte = (uint32_t)k * 512 + ((((uint32_t)n >> 3) ^ (k & 7)) << 4) + ((n * 2) & 15);
    g_B[(size_t)c * 16384 + byte / 2] = __float2half(v);
    if (c == 0 && k == 0) g_wt[n] = (n < NOUT) ? W[n * 577] : 0.0f;
}

// ------------- smem layout -------------
// A buffer: 4 image rows x 66 padded px x 64 ch fp16, m-major 128B rows = 33792 B
// B ring: 3 x 32768
#define OFF_A    0
#define OFF_B    33792
#define B_STAGE  32768
#define OFF_STC  (33792 + 3 * 32768)          // 132096: 128 floats
#define OFF_WT   (OFF_STC + 512)
#define OFF_BIAS (OFF_WT + 1024)
#define OFF_SSP  (OFF_BIAS + 1024)            // 128*4 floats
#define SMEM_BYTES (OFF_SSP + 2048)

// ------------- PTX helpers -------------
__device__ __forceinline__ uint32_t smem_u32(const void* p) {
    uint32_t a;
    asm("{ .reg .u64 t; cvta.to.shared.u64 t, %1; cvt.u32.u64 %0, t; }" : "=r"(a) : "l"(p));
    return a;
}
__device__ __forceinline__ void cp16(uint32_t dst, const void* src) {
    asm volatile("cp.async.cg.shared.global [%0], [%1], 16;" :: "r"(dst), "l"(src));
}
__device__ __forceinline__ void cp_commit() { asm volatile("cp.async.commit_group;"); }
__device__ __forceinline__ void cp_wait1() { asm volatile("cp.async.wait_group 1;"); }

__device__ __forceinline__ void ldsm4(uint32_t* r, uint32_t a) {
    asm volatile("ldmatrix.sync.aligned.m8n8.x4.shared.b16 {%0,%1,%2,%3}, [%4];"
                 : "=r"(r[0]), "=r"(r[1]), "=r"(r[2]), "=r"(r[3]) : "r"(a));
}
__device__ __forceinline__ void ldsm4t(uint32_t* r, uint32_t a) {
    asm volatile("ldmatrix.sync.aligned.m8n8.x4.trans.shared.b16 {%0,%1,%2,%3}, [%4];"
                 : "=r"(r[0]), "=r"(r[1]), "=r"(r[2]), "=r"(r[3]) : "r"(a));
}
__device__ __forceinline__ void mma16816(float* d, const uint32_t* a, const uint32_t* b) {
    asm volatile(
        "mma.sync.aligned.m16n8k16.row.col.f32.f16.f16.f32 "
        "{%0,%1,%2,%3}, {%4,%5,%6,%7}, {%8,%9}, {%0,%1,%2,%3};"
        : "+f"(d[0]), "+f"(d[1]), "+f"(d[2]), "+f"(d[3])
        : "r"(a[0]), "r"(a[1]), "r"(a[2]), "r"(a[3]), "r"(b[0]), "r"(b[1]));
}

__device__ __forceinline__ int clamp64(int v) { return v < 0 ? 0 : (v > 63 ? 63 : v); }

// ------------- main kernel: 2 image rows (128 px) x 256 outputs per CTA -------------
// 16 warps (4m x 4n), warp tile 32x64
__global__ void __launch_bounds__(512, 1)
hyp_hmma(const float* __restrict__ x,
         const float* __restrict__ bias,
         float* __restrict__ out) {
    extern __shared__ char smem[];
    const uint32_t sb = smem_u32(smem);
    float* stc   = (float*)(smem + OFF_STC);
    float* swt   = (float*)(smem + OFF_WT);
    float* sbias = (float*)(smem + OFF_BIAS);
    float* ssp   = (float*)(smem + OFF_SSP);

    const int tid  = threadIdx.x;
    const int lane = tid & 31;
    const int warp = tid >> 5;
    const int wm = warp >> 2;          // 0..3 -> m offset 32*wm
    const int wn = warp & 3;           // 0..3 -> n offset 64*wn

    const int blk  = blockIdx.x;       // 1024 = 32 batches * 32 row-pairs
    const int bimg = blk >> 5;
    const int y0   = (blk & 31) * 2;   // 2 image rows
    const float* ximg = x + (size_t)bimg * 64 * 64 * 65;

    // aux: time weights, bias, t_cat
    if (tid < 256) {
        swt[tid]   = g_wt[tid];
        sbias[tid] = (tid < NOUT) ? bias[tid] : 0.0f;
    }
    if (tid < 128) {
        int iy = tid >> 6, ix = tid & 63;
        float s = 0.0f;
#pragma unroll
        for (int dy = -1; dy <= 1; dy++)
#pragma unroll
            for (int dx = -1; dx <= 1; dx++) {
                int yy = clamp64(y0 + iy + dy);
                int xx = clamp64(ix + dx);
                float t = __ldg(ximg + ((size_t)yy * 64 + xx) * 65);
                s = fmaf(t, t, s);
            }
        stc[tid] = sqrtf(s - 8.0f);
    }

    // ---- B cp.async into ring stage s for tap c (32KB, 64B/thread) ----
    auto loadB = [&](int c, int s) {
        const char* srcB = (const char*)g_B + (size_t)c * 32768;
        uint32_t dstB = sb + OFF_B + s * B_STAGE;
#pragma unroll
        for (int r = 0; r < 4; r++) {
            int u = tid + r * 512;
            cp16(dstB + u * 16, srcB + u * 16);
        }
    };

    // prologue: 2 B stages in flight + one-time A conversion (4 rows x 66 px x 64 ch)
    loadB(0, 0);
    cp_commit();
    loadB(1, 1);
    cp_commit();
    {
        char* aP = smem + OFF_A;
        for (int idx = tid; idx < 4 * 66 * 4; idx += 512) {
            int brow = idx >> 2;            // 0..263
            int q    = idx & 3;             // 16-channel quarter
            int r    = brow / 66;
            int col  = brow - r * 66;
            int yy = clamp64(y0 + r - 1);
            int xx = clamp64(col - 1);
            const float* src = ximg + ((size_t)yy * 64 + xx) * 65 + 1 + q * 16;
            uint32_t w[8];
#pragma unroll
            for (int u = 0; u < 8; u++) {
                float v0 = __ldg(src + 2 * u);
                float v1 = __ldg(src + 2 * u + 1);
                __half2 hv = __floats2half2_rn(v0, v1);
                w[u] = *(uint32_t*)&hv;
            }
            int kc = q * 2;
            uint32_t b0 = (uint32_t)brow * 128 + ((((uint32_t)(kc + 0)) ^ (brow & 7)) << 4);
            uint32_t b1 = (uint32_t)brow * 128 + ((((uint32_t)(kc + 1)) ^ (brow & 7)) << 4);
            *(uint4*)(aP + b0) = make_uint4(w[0], w[1], w[2], w[3]);
            *(uint4*)(aP + b1) = make_uint4(w[4], w[5], w[6], w[7]);
        }
    }

    float acc[2][8][4];
#pragma unroll
    for (int i = 0; i < 2; i++)
#pragma unroll
        for (int j = 0; j < 8; j++)
#pragma unroll
            for (int r = 0; r < 4; r++) acc[i][j][r] = 0.0f;

    const int selm = (lane >> 3) & 1;
    const int selk = lane >> 4;
    const int lr   = lane & 7;
    // warp's pixel block: m0 = wm*32; iy constant within block
    const int iyw  = (wm * 32) >> 6;       // 0 or 1
    const int ix0  = (wm * 32) & 63;       // 0 or 32

    for (int c = 0; c < NCHUNK; c++) {
        cp_wait1();
        __syncthreads();
        const int s = c % 3;
        if (c + 2 < NCHUNK) {
            loadB(c + 2, (c + 2) % 3);
            cp_commit();
        }

        const int dy = c / 3 - 1, dx = c % 3 - 1;
        const int arow0 = (iyw + dy + 1) * 66 + (ix0 + dx + 1);
        const uint32_t baseB = sb + OFF_B + s * B_STAGE;

#pragma unroll
        for (int ks = 0; ks < 4; ks++) {
            const int k0 = ks * 16;
            const int kk = k0 + selk * 8;
            uint32_t ah[2][4];
#pragma unroll
            for (int i = 0; i < 2; i++) {
                int row = arow0 + i * 16 + selm * 8 + lr;
                uint32_t byte = (uint32_t)row * 128 + ((((uint32_t)(kk >> 3)) ^ (row & 7)) << 4);
                ldsm4(ah[i], sb + OFF_A + byte);
            }
            const int kb = k0 + selm * 8 + lr;
#pragma unroll
            for (int jn = 0; jn < 4; jn++) {
                int n0 = wn * 64 + jn * 16;
                int nn = n0 + selk * 8;
                uint32_t byte = (uint32_t)kb * 512 + ((((uint32_t)(nn >> 3)) ^ (kb & 7)) << 4);
                uint32_t r4[4];
                ldsm4t(r4, baseB + byte);
                uint32_t bf0[2] = {r4[0], r4[1]};
                uint32_t bf1[2] = {r4[2], r4[3]};
#pragma unroll
                for (int i = 0; i < 2; i++) {
                    mma16816(acc[i][jn * 2 + 0], ah[i], bf0);
                    mma16816(acc[i][jn * 2 + 1], ah[i], bf1);
                }
            }
        }
    }

    // ---------------- epilogue: direct stores ----------------
    const int q  = lane >> 2;
    const int c2 = (lane & 3) * 2;
    const size_t gbase = (size_t)blk * 128 * 256;

#pragma unroll
    for (int i = 0; i < 2; i++) {
#pragma unroll
        for (int rr = 0; rr < 2; rr++) {
            int p = wm * 32 + i * 16 + rr * 8 + q;    // 0..127
            float tc = stc[p];
            float ssq = 0.0f;
            float* zrow = out + gbase + (size_t)p * 256 + 1;
#pragma unroll
            for (int j = 0; j < 8; j++) {
                int o0 = wn * 64 + j * 8 + c2;
                float z0 = acc[i][j][rr * 2 + 0] + tc * swt[o0] + sbias[o0];
                float z1 = acc[i][j][rr * 2 + 1] + tc * swt[o0 + 1] + sbias[o0 + 1];
                ssq = fmaf(z0, z0, fmaf(z1, z1, ssq));
                zrow[o0] = z0;
                if (o0 + 1 < NOUT) zrow[o0 + 1] = z1;
            }
            ssq += __shfl_xor_sync(0xffffffffu, ssq, 1);
            ssq += __shfl_xor_sync(0xffffffffu, ssq, 2);
            if ((lane & 3) == 0) ssp[p * 4 + wn] = ssq;
        }
    }
    __syncthreads();
    if (tid < 128) {
        float ssum = ssp[tid * 4] + ssp[tid * 4 + 1] + ssp[tid * 4 + 2] + ssp[tid * 4 + 3];
        out[gbase + (size_t)tid * 256] = sqrtf(1.0f + ssum);
    }
}

// ------------- launch -------------
extern "C" void kernel_launch(void* const* d_in, const int* in_sizes, int n_in,
                              void* d_out, int out_size) {
    const float* x = (const float*)d_in[0];   // (32,64,64,65)
    const float* W = (const float*)d_in[1];   // (255,577)
    const float* b = (const float*)d_in[2];   // (255)
    float* out = (float*)d_out;               // (32,64,64,256)

    prep_W<<<dim3(NCHUNK, 64), 256>>>(W);

    cudaFuncSetAttribute(hyp_hmma, cudaFuncAttributeMaxDynamicSharedMemorySize, SMEM_BYTES);
    hyp_hmma<<<1024, 512, SMEM_BYTES>>>(x, b, out);
}

// round 12
// speedup vs baseline: 1.1904x; 1.0808x over previous
#include <cuda_runtime.h>
#include <cuda_fp16.h>
#include <cstdint>
#include <math.h>

#define NOUT 255
#define NCHUNK 9

// ------------- prepped weights -------------
// Per chunk c: B tile 64(k) x 256(n) fp16, pre-swizzled:
//   byte(k,n) = k*512 + (((n>>3) ^ (k&7))<<4) + ((n*2)&15)
__device__ __half g_B[NCHUNK * 64 * 256];
__device__ float g_wt[256];

__global__ void prep_W(const float* __restrict__ W) {
    int c = blockIdx.x;
    int k = blockIdx.y;
    int n = threadIdx.x;
    float v = 0.0f;
    if (n < NOUT) v = W[n * 577 + 1 + c * 64 + k];
    uint32_t byte = (uint32_t)k * 512 + ((((uint32_t)n >> 3) ^ (k & 7)) << 4) + ((n * 2) & 15);
    g_B[(size_t)c * 16384 + byte / 2] = __float2half(v);
    if (c == 0 && k == 0) g_wt[n] = (n < NOUT) ? W[n * 577] : 0.0f;
}

// ------------- smem layout -------------
// A buffer: 3 image rows x 66 padded px x 64 ch fp16, m-major 128B rows = 25344 B
// B stages: 2 x 32768
#define OFF_A    0
#define OFF_B    25344
#define B_STAGE  32768
#define OFF_STC  (25344 + 2 * 32768)      // 90880: 64 floats
#define OFF_WT   (OFF_STC + 256)
#define OFF_BIAS (OFF_WT + 1024)
#define OFF_SSP  (OFF_BIAS + 1024)        // 64*4 floats
#define SMEM_BYTES (OFF_SSP + 1024)       // 94208

// ------------- PTX helpers -------------
__device__ __forceinline__ uint32_t smem_u32(const void* p) {
    uint32_t a;
    asm("{ .reg .u64 t; cvta.to.shared.u64 t, %1; cvt.u32.u64 %0, t; }" : "=r"(a) : "l"(p));
    return a;
}
__device__ __forceinline__ void cp16(uint32_t dst, const void* src) {
    asm volatile("cp.async.cg.shared.global [%0], [%1], 16;" :: "r"(dst), "l"(src));
}
__device__ __forceinline__ void cp_commit() { asm volatile("cp.async.commit_group;"); }
__device__ __forceinline__ void cp_wait_all() { asm volatile("cp.async.wait_group 0;"); }

__device__ __forceinline__ void ldsm4(uint32_t* r, uint32_t a) {
    asm volatile("ldmatrix.sync.aligned.m8n8.x4.shared.b16 {%0,%1,%2,%3}, [%4];"
                 : "=r"(r[0]), "=r"(r[1]), "=r"(r[2]), "=r"(r[3]) : "r"(a));
}
__device__ __forceinline__ void ldsm4t(uint32_t* r, uint32_t a) {
    asm volatile("ldmatrix.sync.aligned.m8n8.x4.trans.shared.b16 {%0,%1,%2,%3}, [%4];"
                 : "=r"(r[0]), "=r"(r[1]), "=r"(r[2]), "=r"(r[3]) : "r"(a));
}
__device__ __forceinline__ void mma16816(float* d, const uint32_t* a, const uint32_t* b) {
    asm volatile(
        "mma.sync.aligned.m16n8k16.row.col.f32.f16.f16.f32 "
        "{%0,%1,%2,%3}, {%4,%5,%6,%7}, {%8,%9}, {%0,%1,%2,%3};"
        : "+f"(d[0]), "+f"(d[1]), "+f"(d[2]), "+f"(d[3])
        : "r"(a[0]), "r"(a[1]), "r"(a[2]), "r"(a[3]), "r"(b[0]), "r"(b[1]));
}

__device__ __forceinline__ int clamp64(int v) { return v < 0 ? 0 : (v > 63 ? 63 : v); }

// ------------- main kernel: 1 image row (64 px) x 256 outputs per CTA -------------
// 8 warps (2m x 4n), warp tile 32x64; 2 CTAs/SM
__global__ void __launch_bounds__(256, 2)
hyp_hmma(const float* __restrict__ x,
         const float* __restrict__ bias,
         float* __restrict__ out) {
    extern __shared__ char smem[];
    const uint32_t sb = smem_u32(smem);
    float* stc   = (float*)(smem + OFF_STC);
    float* swt   = (float*)(smem + OFF_WT);
    float* sbias = (float*)(smem + OFF_BIAS);
    float* ssp   = (float*)(smem + OFF_SSP);

    const int tid  = threadIdx.x;
    const int lane = tid & 31;
    const int warp = tid >> 5;
    const int wm = warp >> 2;          // 0..1 -> m offset 32*wm
    const int wn = warp & 3;           // 0..3 -> n offset 64*wn

    const int blk  = blockIdx.x;       // 2048 = 32 batches * 64 rows
    const int bimg = blk >> 6;
    const int y0   = blk & 63;         // single image row
    const float* ximg = x + (size_t)bimg * 64 * 64 * 65;

    // aux: time weights, bias, t_cat
    swt[tid]   = g_wt[tid];
    sbias[tid] = (tid < NOUT) ? bias[tid] : 0.0f;
    if (tid < 64) {
        float s = 0.0f;
#pragma unroll
        for (int dy = -1; dy <= 1; dy++)
#pragma unroll
            for (int dx = -1; dx <= 1; dx++) {
                int yy = clamp64(y0 + dy);
                int xx = clamp64(tid + dx);
                float t = __ldg(ximg + ((size_t)yy * 64 + xx) * 65);
                s = fmaf(t, t, s);
            }
        stc[tid] = sqrtf(s - 8.0f);
    }

    // ---- B cp.async into stage s for tap c (32KB, 128B/thread) ----
    auto loadB = [&](int c, int s) {
        const char* srcB = (const char*)g_B + (size_t)c * 32768;
        uint32_t dstB = sb + OFF_B + s * B_STAGE;
#pragma unroll
        for (int r = 0; r < 8; r++) {
            int u = tid + r * 256;
            cp16(dstB + u * 16, srcB + u * 16);
        }
    };

    // prologue: first B stage + one-time A conversion (3 rows x 66 px x 64 ch)
    loadB(0, 0);
    cp_commit();
    {
        char* aP = smem + OFF_A;
        for (int idx = tid; idx < 3 * 66 * 4; idx += 256) {
            int brow = idx >> 2;            // 0..197
            int q    = idx & 3;             // 16-channel quarter
            int r    = brow / 66;
            int col  = brow - r * 66;
            int yy = clamp64(y0 + r - 1);
            int xx = clamp64(col - 1);
            const float* src = ximg + ((size_t)yy * 64 + xx) * 65 + 1 + q * 16;
            uint32_t w[8];
#pragma unroll
            for (int u = 0; u < 8; u++) {
                float v0 = __ldg(src + 2 * u);
                float v1 = __ldg(src + 2 * u + 1);
                __half2 hv = __floats2half2_rn(v0, v1);
                w[u] = *(uint32_t*)&hv;
            }
            int kc = q * 2;
            uint32_t b0 = (uint32_t)brow * 128 + ((((uint32_t)(kc + 0)) ^ (brow & 7)) << 4);
            uint32_t b1 = (uint32_t)brow * 128 + ((((uint32_t)(kc + 1)) ^ (brow & 7)) << 4);
            *(uint4*)(aP + b0) = make_uint4(w[0], w[1], w[2], w[3]);
            *(uint4*)(aP + b1) = make_uint4(w[4], w[5], w[6], w[7]);
        }
    }

    float acc[2][8][4];
#pragma unroll
    for (int i = 0; i < 2; i++)
#pragma unroll
        for (int j = 0; j < 8; j++)
#pragma unroll
            for (int r = 0; r < 4; r++) acc[i][j][r] = 0.0f;

    const int selm = (lane >> 3) & 1;
    const int selk = lane >> 4;
    const int lr   = lane & 7;

    for (int c = 0; c < NCHUNK; c++) {
        cp_wait_all();
        __syncthreads();
        const int s = c & 1;
        if (c + 1 < NCHUNK) {
            loadB(c + 1, s ^ 1);
            cp_commit();
        }

        const int dy = c / 3 - 1, dx = c % 3 - 1;
        const int arow0 = (dy + 1) * 66 + dx + 1 + wm * 32;
        const uint32_t baseB = sb + OFF_B + s * B_STAGE;

#pragma unroll
        for (int ks = 0; ks < 4; ks++) {
            const int k0 = ks * 16;
            const int kk = k0 + selk * 8;
            uint32_t ah[2][4];
#pragma unroll
            for (int i = 0; i < 2; i++) {
                int row = arow0 + i * 16 + selm * 8 + lr;
                uint32_t byte = (uint32_t)row * 128 + ((((uint32_t)(kk >> 3)) ^ (row & 7)) << 4);
                ldsm4(ah[i], sb + OFF_A + byte);
            }
            const int kb = k0 + selm * 8 + lr;
#pragma unroll
            for (int jn = 0; jn < 4; jn++) {
                int n0 = wn * 64 + jn * 16;
                int nn = n0 + selk * 8;
                uint32_t byte = (uint32_t)kb * 512 + ((((uint32_t)(nn >> 3)) ^ (kb & 7)) << 4);
                uint32_t r4[4];
                ldsm4t(r4, baseB + byte);
                uint32_t bf0[2] = {r4[0], r4[1]};
                uint32_t bf1[2] = {r4[2], r4[3]};
#pragma unroll
                for (int i = 0; i < 2; i++) {
                    mma16816(acc[i][jn * 2 + 0], ah[i], bf0);
                    mma16816(acc[i][jn * 2 + 1], ah[i], bf1);
                }
            }
        }
    }

    // ---------------- epilogue: direct stores ----------------
    const int q  = lane >> 2;
    const int c2 = (lane & 3) * 2;
    const size_t gbase = (size_t)blk * 64 * 256;

#pragma unroll
    for (int i = 0; i < 2; i++) {
#pragma unroll
        for (int rr = 0; rr < 2; rr++) {
            int p = wm * 32 + i * 16 + rr * 8 + q;    // 0..63
            float tc = stc[p];
            float ssq = 0.0f;
            float* zrow = out + gbase + (size_t)p * 256 + 1;
#pragma unroll
            for (int j = 0; j < 8; j++) {
                int o0 = wn * 64 + j * 8 + c2;
                float z0 = acc[i][j][rr * 2 + 0] + tc * swt[o0] + sbias[o0];
                float z1 = acc[i][j][rr * 2 + 1] + tc * swt[o0 + 1] + sbias[o0 + 1];
                ssq = fmaf(z0, z0, fmaf(z1, z1, ssq));
                zrow[o0] = z0;
                if (o0 + 1 < NOUT) zrow[o0 + 1] = z1;
            }
            ssq += __shfl_xor_sync(0xffffffffu, ssq, 1);
            ssq += __shfl_xor_sync(0xffffffffu, ssq, 2);
            if ((lane & 3) == 0) ssp[p * 4 + wn] = ssq;
        }
    }
    __syncthreads();
    if (tid < 64) {
        float ssum = ssp[tid * 4] + ssp[tid * 4 + 1] + ssp[tid * 4 + 2] + ssp[tid * 4 + 3];
        out[gbase + (size_t)tid * 256] = sqrtf(1.0f + ssum);
    }
}

// ------------- launch -------------
extern "C" void kernel_launch(void* const* d_in, const int* in_sizes, int n_in,
                              void* d_out, int out_size) {
    const float* x = (const float*)d_in[0];   // (32,64,64,65)
    const float* W = (const float*)d_in[1];   // (255,577)
    const float* b = (const float*)d_in[2];   // (255)
    float* out = (float*)d_out;               // (32,64,64,256)

    prep_W<<<dim3(NCHUNK, 64), 256>>>(W);

    cudaFuncSetAttribute(hyp_hmma, cudaFuncAttributeMaxDynamicSharedMemorySize, SMEM_BYTES);
    hyp_hmma<<<2048, 256, SMEM_BYTES>>>(x, b, out);
}